// round 5
// baseline (speedup 1.0000x reference)
#include <cuda_runtime.h>
#include <cuda_bf16.h>

// CapsuleRoutingPooling collapses analytically:
// softmax over a size-1 axis == 1 -> routing loop is a no-op.
// out = squash( 2x2 sum-pool over spatial of the D=16 vectors ).
//
// Shapes: B=16, C=64, H=W=64, D=16, k=2 -> nH=nW=32,
// output vectors NVEC = 16*64*32*32 = 1,048,576.
//
// Layout: 4 lanes per output vector (one float4 each); each thread handles
// TWO vectors (near half + far half) -> 8 independent 16B loads in flight.
// Default-cached loads (ldcs on loads measured slightly worse sector
// behavior); __stcs streaming stores (output never re-read).
// Oversubscribed grid (8192 x 256) — persistent single-wave regressed (R3).

static constexpr int NVEC = 16 * 64 * 32 * 32;     // 1,048,576
static constexpr int HALF = NVEC / 2;              // 524,288
static constexpr int NTHREADS_TOTAL = HALF * 4;    // 2,097,152

__device__ __forceinline__ float4 squash4(float4 s) {
    float sq = s.x * s.x + s.y * s.y + s.z * s.z + s.w * s.w;
    sq += __shfl_xor_sync(0xffffffffu, sq, 1);
    sq += __shfl_xor_sync(0xffffffffu, sq, 2);
    float scale = sq / ((1.0f + sq) * (sqrtf(sq) + 1e-8f));
    float4 o;
    o.x = s.x * scale; o.y = s.y * scale;
    o.z = s.z * scale; o.w = s.w * scale;
    return o;
}

__global__ void __launch_bounds__(256)
capsule_pool_squash_kernel(const float* __restrict__ inp, float* __restrict__ out) {
    int gid  = blockIdx.x * blockDim.x + threadIdx.x;
    int v0   = gid >> 2;          // first output vector (near half)
    int lane = gid & 3;
    int v1   = v0 + HALF;         // second output vector (far half)

    const float4* __restrict__ in4 = (const float4*)inp;

    // index math for both vectors, then all 8 loads back-to-back (MLP=8)
    int bc0 = v0 >> 10, t0 = v0 & 1023;
    int bc1 = v1 >> 10, t1 = v1 & 1023;
    int base0 = (bc0 * 64 + ((t0 >> 5) << 1)) * 256 + ((t0 & 31) << 3) + lane;
    int base1 = (bc1 * 64 + ((t1 >> 5) << 1)) * 256 + ((t1 & 31) << 3) + lane;

    float4 a00 = in4[base0];
    float4 a01 = in4[base0 + 4];
    float4 a10 = in4[base0 + 256];
    float4 a11 = in4[base0 + 260];
    float4 b00 = in4[base1];
    float4 b01 = in4[base1 + 4];
    float4 b10 = in4[base1 + 256];
    float4 b11 = in4[base1 + 260];

    float4 sa, sb;
    sa.x = (a00.x + a01.x) + (a10.x + a11.x);
    sa.y = (a00.y + a01.y) + (a10.y + a11.y);
    sa.z = (a00.z + a01.z) + (a10.z + a11.z);
    sa.w = (a00.w + a01.w) + (a10.w + a11.w);
    sb.x = (b00.x + b01.x) + (b10.x + b11.x);
    sb.y = (b00.y + b01.y) + (b10.y + b11.y);
    sb.z = (b00.z + b01.z) + (b10.z + b11.z);
    sb.w = (b00.w + b01.w) + (b10.w + b11.w);

    float4 oa = squash4(sa);
    float4 ob = squash4(sb);

    float4* __restrict__ out4 = (float4*)out;
    __stcs(&out4[(v0 << 2) + lane], oa);
    __stcs(&out4[(v1 << 2) + lane], ob);
}

extern "C" void kernel_launch(void* const* d_in, const int* in_sizes, int n_in,
                              void* d_out, int out_size) {
    const float* inp = (const float*)d_in[0];
    float* out = (float*)d_out;
    int threads = 256;
    int blocks = NTHREADS_TOTAL / threads;   // 8192
    capsule_pool_squash_kernel<<<blocks, threads>>>(inp, out);
}

// round 6
// speedup vs baseline: 1.0012x; 1.0012x over previous
#include <cuda_runtime.h>
#include <cuda_bf16.h>

// CapsuleRoutingPooling collapses analytically:
// softmax over a size-1 axis == 1 -> routing loop is a no-op.
// out = squash( 2x2 sum-pool over spatial of the D=16 vectors ).
//
// Shapes: B=16, C=64, H=W=64, D=16, k=2 -> nH=nW=32, NVEC = 1,048,576.
//
// Fully-contiguous-load layout: each warp owns a segment of 8 pixels
// (512 B) in a row pair. Two load instructions per warp, each a perfectly
// dense 512 B (4 full 128 B lines). Vertical (kh) sum in registers;
// horizontal (kw) sum via shfl_xor(...,4). Per-vector norm via shfl_xor 1,2.
// Half-warp predicated but fully-coalesced 256 B stores (__stcs).

static constexpr int NVEC   = 16 * 64 * 32 * 32;   // 1,048,576 output vectors
static constexpr int NWARPS = NVEC / 4;            // 4 vectors per warp
static constexpr int NTHREADS_TOTAL = NWARPS * 32; // 8,388,608
static constexpr int THREADS = 256;
static constexpr int BLOCKS  = NTHREADS_TOTAL / THREADS;  // 32768

__global__ void __launch_bounds__(THREADS)
capsule_pool_squash_kernel(const float* __restrict__ inp, float* __restrict__ out) {
    int gid  = blockIdx.x * THREADS + threadIdx.x;
    int w_id = gid >> 5;        // warp id
    int lane = gid & 31;

    // warp -> (bc, nh, nwb): 256 warps per bc, 8 warps per nh row
    int bc  = w_id >> 8;        // b*C + c  (0..1023)
    int t   = w_id & 255;
    int nh  = t >> 3;           // 0..31
    int nwb = t & 7;            // block of 4 output columns

    const float4* __restrict__ in4 = (const float4*)inp;

    // input row (b,c,h) = 256 float4s; segment = 8 pixels = 32 float4s
    int rowbase0 = (bc * 64 + (nh << 1)) * 256 + (nwb << 5) + lane;

    // two perfectly dense 512B warp loads (rows 2nh and 2nh+1)
    float4 r0 = in4[rowbase0];
    float4 r1 = in4[rowbase0 + 256];

    // vertical (kh) sum
    float4 s;
    s.x = r0.x + r1.x;
    s.y = r0.y + r1.y;
    s.z = r0.z + r1.z;
    s.w = r0.w + r1.w;

    // horizontal (kw) sum: lane l holds pixel w = nwb*8 + (l>>2), d-chunk l&3.
    // xor 4 pairs even/odd w with the same d-chunk.
    s.x += __shfl_xor_sync(0xffffffffu, s.x, 4);
    s.y += __shfl_xor_sync(0xffffffffu, s.y, 4);
    s.z += __shfl_xor_sync(0xffffffffu, s.z, 4);
    s.w += __shfl_xor_sync(0xffffffffu, s.w, 4);

    // squared norm over D=16 (4 lanes per vector)
    float sq = s.x * s.x + s.y * s.y + s.z * s.z + s.w * s.w;
    sq += __shfl_xor_sync(0xffffffffu, sq, 1);
    sq += __shfl_xor_sync(0xffffffffu, sq, 2);

    float scale = sq / ((1.0f + sq) * (sqrtf(sq) + 1e-8f));

    float4 o;
    o.x = s.x * scale;
    o.y = s.y * scale;
    o.z = s.z * scale;
    o.w = s.w * scale;

    // output vector: nw = nwb*4 + (lane>>3); lanes with (lane&4)==0 write.
    // Active lanes 0-3,8-11,16-19,24-27 -> one contiguous 256B store.
    if ((lane & 4) == 0) {
        int v = bc * 1024 + (nh << 5) + (nwb << 2) + (lane >> 3);
        __stcs(&((float4*)out)[(v << 2) + (lane & 3)], o);
    }
}

extern "C" void kernel_launch(void* const* d_in, const int* in_sizes, int n_in,
                              void* d_out, int out_size) {
    const float* inp = (const float*)d_in[0];
    float* out = (float*)d_out;
    capsule_pool_squash_kernel<<<BLOCKS, THREADS>>>(inp, out);
}

// round 7
// speedup vs baseline: 1.0091x; 1.0079x over previous
#include <cuda_runtime.h>
#include <cuda_bf16.h>

// CapsuleRoutingPooling collapses analytically:
// softmax over a size-1 axis == 1 -> the dynamic-routing loop is a no-op
// w.r.t. the output. Kernel = squash( 2x2 sum-pool of the D=16 vectors ).
//
// Shapes: B=16, C=64, H=W=64, D=16, k=2 -> nH=nW=32,
// output vectors = 16*64*32*32 = 1,048,576.
//
// FINAL (Round-4 configuration, best bench 53.09us, revalidated):
// 4 threads per output vector, one float4 each; plain cached loads;
// __stcs streaming stores; oversubscribed grid 16384 x 256.
// Measured at ~6.55 TB/s HBM (82% of spec) — the achievable ceiling for
// this 4:1 read:write streaming mix. ILP depth, load cache hints, dense
// request shaping, and persistent grids were all measured neutral-or-worse
// (R2/R3/R5/R6); traffic (320 MB) is the mandatory minimum.

static constexpr int NVEC = 16 * 64 * 32 * 32;     // output vectors
static constexpr int NTHREADS_TOTAL = NVEC * 4;    // 4,194,304

__global__ void __launch_bounds__(256)
capsule_pool_squash_kernel(const float* __restrict__ inp, float* __restrict__ out) {
    int gid  = blockIdx.x * blockDim.x + threadIdx.x;
    int v    = gid >> 2;      // output vector id
    int lane = gid & 3;       // which float4 of the D=16 vector

    // v = ((bc)*32 + nh)*32 + nw
    int bc = v >> 10;         // b*C + c   (0..1023)
    int t  = v & 1023;
    int nh = t >> 5;
    int nw = t & 31;

    // input float4 indexing: row (b,c,h) has W*D/4 = 256 float4s; w step = D/4 = 4
    const float4* __restrict__ in4 = (const float4*)inp;
    int base4 = (bc * 64 + (nh << 1)) * 256 + (nw << 3) + lane;

    float4 p00 = in4[base4];
    float4 p01 = in4[base4 + 4];
    float4 p10 = in4[base4 + 256];
    float4 p11 = in4[base4 + 260];

    float4 s;
    s.x = (p00.x + p01.x) + (p10.x + p11.x);
    s.y = (p00.y + p01.y) + (p10.y + p11.y);
    s.z = (p00.z + p01.z) + (p10.z + p11.z);
    s.w = (p00.w + p01.w) + (p10.w + p11.w);

    // squared norm over D=16: reduce across the 4 lanes of this vector
    float sq = s.x * s.x + s.y * s.y + s.z * s.z + s.w * s.w;
    sq += __shfl_xor_sync(0xffffffffu, sq, 1);
    sq += __shfl_xor_sync(0xffffffffu, sq, 2);

    // squash scale: sq/(1+sq) * 1/(sqrt(sq)+1e-8)
    float scale = sq / ((1.0f + sq) * (sqrtf(sq) + 1e-8f));

    float4 o;
    o.x = s.x * scale;
    o.y = s.y * scale;
    o.z = s.z * scale;
    o.w = s.w * scale;

    __stcs(&((float4*)out)[(v << 2) + lane], o);
}

extern "C" void kernel_launch(void* const* d_in, const int* in_sizes, int n_in,
                              void* d_out, int out_size) {
    const float* inp = (const float*)d_in[0];
    float* out = (float*)d_out;
    int threads = 256;
    int blocks = NTHREADS_TOTAL / threads;   // 16384
    capsule_pool_squash_kernel<<<blocks, threads>>>(inp, out);
}